// round 2
// baseline (speedup 1.0000x reference)
#include <cuda_runtime.h>
#include <cuda_bf16.h>
#include <cstdint>

// Problem constants
#define BB   256   // batch
#define LL   256   // seq len
#define IN_  256   // input dim
#define DD   128   // hidden dim
#define HH   64    // DD/2

// ---------------------------------------------------------------------------
// packed f32x2 helpers (FFMA2 — only reachable via PTX fma.rn.f32x2)
// ---------------------------------------------------------------------------
__device__ __forceinline__ unsigned long long ffma2(unsigned long long a,
                                                    unsigned long long b,
                                                    unsigned long long c) {
    unsigned long long d;
    asm("fma.rn.f32x2 %0, %1, %2, %3;" : "=l"(d) : "l"(a), "l"(b), "l"(c));
    return d;
}
__device__ __forceinline__ unsigned long long pack2(float x) {
    unsigned long long r;
    asm("mov.b64 %0, {%1, %1};" : "=l"(r) : "f"(x));
    return r;
}
__device__ __forceinline__ unsigned long long packpair(float lo, float hi) {
    unsigned long long r;
    asm("mov.b64 %0, {%1, %2};" : "=l"(r) : "f"(lo), "f"(hi));
    return r;
}
__device__ __forceinline__ float2 unpack2(unsigned long long v) {
    float2 f;
    asm("mov.b64 {%0, %1}, %2;" : "=f"(f.x), "=f"(f.y) : "l"(v));
    return f;
}

// ---------------------------------------------------------------------------
// Scratch (device globals; no runtime allocation allowed)
// ---------------------------------------------------------------------------
__device__ float g_X[(size_t)BB * LL * 384];  // [b][t][mat*128+d], mat: 0=r 1=z 2=h
__device__ float g_a[(size_t)BB * LL];        // attention gate a[b][t]

// ---------------------------------------------------------------------------
// Kernel A: projection GEMM  out[i][my*128+j] = dot(x[i], W[j]) + bias[j]
//   M = B*L = 65536, N = 128 per matrix (grid.y selects r/z/h), K = 256
//   BM=128, BN=128, BK=16; 256 threads; 8x8 outputs/thread via f32x2 pairs
// ---------------------------------------------------------------------------
__global__ __launch_bounds__(256, 2) void proj_gemm(
    const float* __restrict__ x,
    const float* __restrict__ wr, const float* __restrict__ br,
    const float* __restrict__ wz, const float* __restrict__ bz,
    const float* __restrict__ wh, const float* __restrict__ bh,
    float* __restrict__ out)
{
    __shared__ float xs[16][128 + 4];
    __shared__ float ws[16][128 + 4];

    const int my = blockIdx.y;
    const float* __restrict__ W  = (my == 0) ? wr : (my == 1 ? wz : wh);
    const float* __restrict__ Bv = (my == 0) ? br : (my == 1 ? bz : bh);

    const int tid = threadIdx.x;
    const int tx = tid & 15;        // 0..15 -> j block of 8
    const int ty = tid >> 4;        // 0..15 -> i block of 8
    const int i0 = blockIdx.x * 128;

    unsigned long long acc[8][4];
#pragma unroll
    for (int a = 0; a < 8; a++)
#pragma unroll
        for (int b = 0; b < 4; b++) acc[a][b] = 0ULL;

    const int lrow = tid >> 2;      // 0..63
    const int lc4  = tid & 3;       // 0..3

    for (int k0 = 0; k0 < 256; k0 += 16) {
#pragma unroll
        for (int r = 0; r < 2; r++) {
            int row = lrow + r * 64;
            float4 v = *(const float4*)&x[(size_t)(i0 + row) * 256 + k0 + lc4 * 4];
            xs[lc4 * 4 + 0][row] = v.x;
            xs[lc4 * 4 + 1][row] = v.y;
            xs[lc4 * 4 + 2][row] = v.z;
            xs[lc4 * 4 + 3][row] = v.w;
        }
#pragma unroll
        for (int r = 0; r < 2; r++) {
            int row = lrow + r * 64;
            float4 v = *(const float4*)&W[(size_t)row * 256 + k0 + lc4 * 4];
            ws[lc4 * 4 + 0][row] = v.x;
            ws[lc4 * 4 + 1][row] = v.y;
            ws[lc4 * 4 + 2][row] = v.z;
            ws[lc4 * 4 + 3][row] = v.w;
        }
        __syncthreads();

#pragma unroll
        for (int k = 0; k < 16; k++) {
            float4 xa = *(const float4*)&xs[k][ty * 8];
            float4 xb = *(const float4*)&xs[k][ty * 8 + 4];
            float4 wa = *(const float4*)&ws[k][tx * 8];
            float4 wb = *(const float4*)&ws[k][tx * 8 + 4];
            unsigned long long wp0 = packpair(wa.x, wa.y);
            unsigned long long wp1 = packpair(wa.z, wa.w);
            unsigned long long wp2 = packpair(wb.x, wb.y);
            unsigned long long wp3 = packpair(wb.z, wb.w);
            float xv[8] = {xa.x, xa.y, xa.z, xa.w, xb.x, xb.y, xb.z, xb.w};
#pragma unroll
            for (int ii = 0; ii < 8; ii++) {
                unsigned long long xp = pack2(xv[ii]);
                acc[ii][0] = ffma2(xp, wp0, acc[ii][0]);
                acc[ii][1] = ffma2(xp, wp1, acc[ii][1]);
                acc[ii][2] = ffma2(xp, wp2, acc[ii][2]);
                acc[ii][3] = ffma2(xp, wp3, acc[ii][3]);
            }
        }
        __syncthreads();
    }

    // epilogue: add bias, write out
    float bias[8];
#pragma unroll
    for (int j = 0; j < 8; j++) bias[j] = Bv[tx * 8 + j];

#pragma unroll
    for (int ii = 0; ii < 8; ii++) {
        int irow = i0 + ty * 8 + ii;
        float* orow = &out[(size_t)irow * 384 + my * 128 + tx * 8];
        float2 p0 = unpack2(acc[ii][0]);
        float2 p1 = unpack2(acc[ii][1]);
        float2 p2 = unpack2(acc[ii][2]);
        float2 p3 = unpack2(acc[ii][3]);
        float4 o0 = make_float4(p0.x + bias[0], p0.y + bias[1],
                                p1.x + bias[2], p1.y + bias[3]);
        float4 o1 = make_float4(p2.x + bias[4], p2.y + bias[5],
                                p3.x + bias[6], p3.y + bias[7]);
        *(float4*)&orow[0] = o0;
        *(float4*)&orow[4] = o1;
    }
}

// ---------------------------------------------------------------------------
// Kernel A2: a[b][t] = sigmoid(dot(x[b][t], k1 - k2))
//   (softmax over 2 logits, taking component 0 == sigmoid of the difference)
//   one warp per row; 8 warps per CTA
// ---------------------------------------------------------------------------
__global__ __launch_bounds__(256) void a_gate_kernel(
    const float* __restrict__ x, const float* __restrict__ k1k2,
    float* __restrict__ ga)
{
    const int warp = threadIdx.x >> 5, lane = threadIdx.x & 31;
    const int row = blockIdx.x * 8 + warp;
    const float* xr = x + (size_t)row * 256;
    float s = 0.f;
#pragma unroll
    for (int r = 0; r < 2; r++) {
        int k = lane * 4 + r * 128;
        float4 xv = *(const float4*)&xr[k];
        float4 a1 = *(const float4*)&k1k2[k];
        float4 a2 = *(const float4*)&k1k2[256 + k];
        s += xv.x * (a1.x - a2.x) + xv.y * (a1.y - a2.y) +
             xv.z * (a1.z - a2.z) + xv.w * (a1.w - a2.w);
    }
#pragma unroll
    for (int off = 16; off > 0; off >>= 1)
        s += __shfl_xor_sync(0xffffffffu, s, off);
    if (lane == 0) ga[row] = 1.f / (1.f + __expf(-s));
}

// ---------------------------------------------------------------------------
// Kernel B: sequential recurrence. 128 CTAs x 2 batches, 512 threads.
//   thread = (d in [0,128), q in [0,4)); warp lanes share q -> m[k] LDS broadcast
//   U rows register-cached as packed f32x2 pairs (96 regs/thread).
//   History buf lives in smem; element [j][e] written+read by the SAME thread.
// ---------------------------------------------------------------------------
__global__ __launch_bounds__(512, 1) void rnn_kernel(
    const float* __restrict__ gX, const float* __restrict__ ga,
    const int* __restrict__ cor,
    const float* __restrict__ ur, const float* __restrict__ uz,
    const float* __restrict__ uh,
    float* __restrict__ out)
{
    extern __shared__ float sm[];
    float* m_sm   = sm;                    // [2][128]              256
    float* part   = sm + 256;              // [3][2][4*128]         3072
    float* xs     = sm + 256 + 3072;       // [2][384]              768
    float* a_sm   = xs + 768;              // [2][256]              512
    int*   cor_sm = (int*)(a_sm + 512);    // [2][256]              512
    float* buf    = (float*)(cor_sm + 512);// [2][257][64]          32896

    const int tid = threadIdx.x;
    const int b0  = blockIdx.x * 2;
    const int d   = tid & 127;
    const int q   = tid >> 7;
    const int kbase = q * 32;

    // register-cache U slices as packed (k, k+1) pairs
    unsigned long long urr[16], uzr[16], uhr[16];
#pragma unroll
    for (int kk = 0; kk < 16; kk++) {
        urr[kk] = *(const unsigned long long*)&ur[d * 128 + kbase + 2 * kk];
        uzr[kk] = *(const unsigned long long*)&uz[d * 128 + kbase + 2 * kk];
        uhr[kk] = *(const unsigned long long*)&uh[d * 128 + kbase + 2 * kk];
    }

    // init: m_0 = 0, buf[:,0,:] = 0; preload a and cor
    if (tid < 256) m_sm[tid] = 0.f;
    if (tid < 128) {
        int bb = tid >> 6;
        buf[bb * 16448 + (tid & 63)] = 0.f;
    }
    {
        int bb = tid >> 8, tt = tid & 255;
        a_sm[tid]   = ga[(size_t)(b0 + bb) * LL + tt];
        cor_sm[tid] = cor[(size_t)(b0 + bb) * LL + tt];
    }
    __syncthreads();

    const unsigned long long* m0p =
        (const unsigned long long*)&m_sm[kbase];
    const unsigned long long* m1p =
        (const unsigned long long*)&m_sm[128 + kbase];

    for (int t = 0; t < LL; t++) {
        // ---- prefetch X[t] for both batches (hidden behind the matvec) ----
        const size_t base0 = ((size_t)b0 * LL + t) * 384;
        const size_t base1 = ((size_t)(b0 + 1) * LL + t) * 384;
        float xpre0 = (tid < 384) ? gX[base0 + tid] : gX[base1 + (tid - 384)];
        float xpre1 = (tid < 256) ? gX[base1 + 128 + tid] : 0.f;

        // ---- matvec: acc over this thread's 32-k slice, both batches ----
        unsigned long long ar0 = 0ULL, ar1 = 0ULL;
        unsigned long long az0 = 0ULL, az1 = 0ULL;
        unsigned long long ah0 = 0ULL, ah1 = 0ULL;
#pragma unroll
        for (int kk = 0; kk < 16; kk++) {
            unsigned long long m0 = m0p[kk];
            unsigned long long m1 = m1p[kk];
            ar0 = ffma2(urr[kk], m0, ar0);
            ar1 = ffma2(urr[kk], m1, ar1);
            az0 = ffma2(uzr[kk], m0, az0);
            az1 = ffma2(uzr[kk], m1, az1);
            ah0 = ffma2(uhr[kk], m0, ah0);
            ah1 = ffma2(uhr[kk], m1, ah1);
        }
        // horizontal add + store partials
        {
            float2 f;
            f = unpack2(ar0); part[0 * 1024 + 0 * 512 + q * 128 + d] = f.x + f.y;
            f = unpack2(ar1); part[0 * 1024 + 1 * 512 + q * 128 + d] = f.x + f.y;
            f = unpack2(az0); part[1 * 1024 + 0 * 512 + q * 128 + d] = f.x + f.y;
            f = unpack2(az1); part[1 * 1024 + 1 * 512 + q * 128 + d] = f.x + f.y;
            f = unpack2(ah0); part[2 * 1024 + 0 * 512 + q * 128 + d] = f.x + f.y;
            f = unpack2(ah1); part[2 * 1024 + 1 * 512 + q * 128 + d] = f.x + f.y;
        }
        // land prefetched X into smem
        xs[tid] = xpre0;
        if (tid < 256) xs[512 + tid] = xpre1;
        __syncthreads();

        // ---- nonlinearity + state update (256 threads: (bb, dd)) ----
        if (tid < 256) {
            const int bb = tid >> 7;
            const int dd = tid & 127;
            const int pb = bb * 512 + dd;
            float sr = part[pb] + part[pb + 128] + part[pb + 256] + part[pb + 384];
            float sz = part[1024 + pb] + part[1024 + pb + 128] +
                       part[1024 + pb + 256] + part[1024 + pb + 384];
            float sh = part[2048 + pb] + part[2048 + pb + 128] +
                       part[2048 + pb + 256] + part[2048 + pb + 384];
            float xr = xs[bb * 384 + dd];
            float xz = xs[bb * 384 + 128 + dd];
            float xh = xs[bb * 384 + 256 + dd];

            float r  = 1.f / (1.f + __expf(-(xr + sr)));
            float z  = 1.f / (1.f + __expf(-(xz + sz)));
            float hv = tanhf(xh + r * sh);
            float mv = m_sm[bb * 128 + dd];
            float h  = (1.f - z) * mv + z * hv;

            out[(((size_t)(b0 + bb) * LL) + t) * DD + dd] = h;

            if (t + 1 < LL) {
                float an = a_sm[bb * 256 + t + 1];
                if (dd < HH) {
                    m_sm[bb * 128 + dd] = an * h;
                } else {
                    // history write & gather: same thread owns buf[*][dd-64]
                    buf[bb * 16448 + (t + 1) * 64 + (dd - HH)] = h;
                    int cn = cor_sm[bb * 256 + t + 1];
                    int ie = (cn == 0) ? (t + 1) : cn;
                    m_sm[bb * 128 + dd] =
                        (1.f - an) * buf[bb * 16448 + ie * 64 + (dd - HH)];
                }
            }
        }
        __syncthreads();
    }
}

// ---------------------------------------------------------------------------
// launch
// ---------------------------------------------------------------------------
extern "C" void kernel_launch(void* const* d_in, const int* in_sizes, int n_in,
                              void* d_out, int out_size)
{
    (void)in_sizes; (void)n_in; (void)out_size;
    const float* x    = (const float*)d_in[0];
    const int*   cor  = (const int*)d_in[1];
    const float* w_r  = (const float*)d_in[2];
    const float* b_r  = (const float*)d_in[3];
    const float* u_r  = (const float*)d_in[4];
    const float* w_z  = (const float*)d_in[5];
    const float* b_z  = (const float*)d_in[6];
    const float* u_z  = (const float*)d_in[7];
    const float* w_h  = (const float*)d_in[8];
    const float* b_h  = (const float*)d_in[9];
    const float* u_h  = (const float*)d_in[10];
    const float* k1k2 = (const float*)d_in[11];
    float* out = (float*)d_out;

    float* gX; cudaGetSymbolAddress((void**)&gX, g_X);
    float* ga; cudaGetSymbolAddress((void**)&ga, g_a);

    // Kernel A: projections (65536 x 384 x 256 fp32 GEMM via f32x2)
    {
        dim3 grid(BB * LL / 128, 3);
        proj_gemm<<<grid, 256>>>(x, w_r, b_r, w_z, b_z, w_h, b_h, gX);
    }
    // Kernel A2: attention gate
    a_gate_kernel<<<BB * LL / 8, 256>>>(x, k1k2, ga);

    // Kernel B: recurrence
    {
        const size_t smemB = (size_t)(256 + 3072 + 768 + 512 + 512 +
                                      2 * 257 * 64) * sizeof(float); // 152064
        cudaFuncSetAttribute(rnn_kernel,
                             cudaFuncAttributeMaxDynamicSharedMemorySize,
                             (int)smemB);
        rnn_kernel<<<128, 512, smemB>>>(gX, ga, cor, u_r, u_z, u_h, out);
    }
}

// round 3
// speedup vs baseline: 1.4043x; 1.4043x over previous
#include <cuda_runtime.h>
#include <cuda_bf16.h>
#include <cstdint>

// Problem constants
#define BB   256   // batch
#define LL   256   // seq len
#define IN_  256   // input dim
#define DD   128   // hidden dim
#define HH   64    // DD/2

// ---------------------------------------------------------------------------
// packed f32x2 helpers (FFMA2)
// ---------------------------------------------------------------------------
__device__ __forceinline__ unsigned long long ffma2(unsigned long long a,
                                                    unsigned long long b,
                                                    unsigned long long c) {
    unsigned long long d;
    asm("fma.rn.f32x2 %0, %1, %2, %3;" : "=l"(d) : "l"(a), "l"(b), "l"(c));
    return d;
}
__device__ __forceinline__ float2 unpack2(unsigned long long v) {
    float2 f;
    asm("mov.b64 {%0, %1}, %2;" : "=f"(f.x), "=f"(f.y) : "l"(v));
    return f;
}
__device__ __forceinline__ unsigned int f2tf32(float f) {
    unsigned int u;
    asm("cvt.rna.tf32.f32 %0, %1;" : "=r"(u) : "f"(f));
    return u;
}

// ---------------------------------------------------------------------------
// Scratch (device globals; no runtime allocation allowed)
// ---------------------------------------------------------------------------
__device__ float g_X[(size_t)BB * LL * 384];  // [b][t][mat*128+d]
__device__ float g_a[(size_t)BB * LL];        // attention gate a[b][t]

// ---------------------------------------------------------------------------
// Kernel A: projection GEMM via tf32 mma.sync (m16n8k8)
//   out[i][my*128+j] = dot(x[i], W[j]) + bias[j]
//   BM=128, BN=128, BK=32; 512 threads; warp grid 4x4, warp tile 32x32
//   double-buffered smem with stride-36 (conflict-free frag loads)
// ---------------------------------------------------------------------------
#define PJ_STRIDE 36
extern __shared__ float pj_sm[];

__global__ __launch_bounds__(512, 1) void proj_gemm_tf32(
    const float* __restrict__ x,
    const float* __restrict__ wr, const float* __restrict__ br,
    const float* __restrict__ wz, const float* __restrict__ bz,
    const float* __restrict__ wh, const float* __restrict__ bh,
    float* __restrict__ out)
{
    float* As = pj_sm;                                // [2][128][36]
    float* Bs = pj_sm + 2 * 128 * PJ_STRIDE;          // [2][128][36]

    const int my = blockIdx.y;
    const float* __restrict__ W  = (my == 0) ? wr : (my == 1 ? wz : wh);
    const float* __restrict__ Bv = (my == 0) ? br : (my == 1 ? bz : bh);

    const int tid  = threadIdx.x;
    const int lane = tid & 31;
    const int wid  = tid >> 5;
    const int wm   = wid & 3;        // 0..3 -> 32-row slab
    const int wn   = wid >> 2;       // 0..3 -> 32-col slab
    const int gid  = lane >> 2;      // 0..7
    const int tid4 = lane & 3;       // 0..3
    const int i0   = blockIdx.x * 128;

    // loader mapping: 4 float4 per thread per tile (2 x, 2 w)
    const int lr = tid >> 3;         // 0..63
    const int lc = tid & 7;          // 0..7 (float4 col)

    float acc[2][4][4];
#pragma unroll
    for (int a = 0; a < 2; a++)
#pragma unroll
        for (int b = 0; b < 4; b++)
#pragma unroll
            for (int c = 0; c < 4; c++) acc[a][b][c] = 0.f;

    float4 sx0, sx1, sw0, sw1;

    // prologue: load tile 0
    {
        const int k0 = 0;
        sx0 = *(const float4*)&x[(size_t)(i0 + lr)      * 256 + k0 + lc * 4];
        sx1 = *(const float4*)&x[(size_t)(i0 + lr + 64) * 256 + k0 + lc * 4];
        sw0 = *(const float4*)&W[(size_t)(lr)      * 256 + k0 + lc * 4];
        sw1 = *(const float4*)&W[(size_t)(lr + 64) * 256 + k0 + lc * 4];
        unsigned int* a0 = (unsigned int*)&As[(size_t)lr * PJ_STRIDE + lc * 4];
        unsigned int* a1 = (unsigned int*)&As[(size_t)(lr + 64) * PJ_STRIDE + lc * 4];
        unsigned int* b0 = (unsigned int*)&Bs[(size_t)lr * PJ_STRIDE + lc * 4];
        unsigned int* b1 = (unsigned int*)&Bs[(size_t)(lr + 64) * PJ_STRIDE + lc * 4];
        a0[0]=f2tf32(sx0.x); a0[1]=f2tf32(sx0.y); a0[2]=f2tf32(sx0.z); a0[3]=f2tf32(sx0.w);
        a1[0]=f2tf32(sx1.x); a1[1]=f2tf32(sx1.y); a1[2]=f2tf32(sx1.z); a1[3]=f2tf32(sx1.w);
        b0[0]=f2tf32(sw0.x); b0[1]=f2tf32(sw0.y); b0[2]=f2tf32(sw0.z); b0[3]=f2tf32(sw0.w);
        b1[0]=f2tf32(sw1.x); b1[1]=f2tf32(sw1.y); b1[2]=f2tf32(sw1.z); b1[3]=f2tf32(sw1.w);
    }
    __syncthreads();

#pragma unroll 1
    for (int t = 0; t < 8; t++) {
        const int cur = t & 1;
        const int nxt = cur ^ 1;
        // prefetch next tile
        if (t < 7) {
            const int k0 = (t + 1) * 32;
            sx0 = *(const float4*)&x[(size_t)(i0 + lr)      * 256 + k0 + lc * 4];
            sx1 = *(const float4*)&x[(size_t)(i0 + lr + 64) * 256 + k0 + lc * 4];
            sw0 = *(const float4*)&W[(size_t)(lr)      * 256 + k0 + lc * 4];
            sw1 = *(const float4*)&W[(size_t)(lr + 64) * 256 + k0 + lc * 4];
        }

        const unsigned int* Au = (const unsigned int*)(As + (size_t)cur * 128 * PJ_STRIDE);
        const unsigned int* Bu = (const unsigned int*)(Bs + (size_t)cur * 128 * PJ_STRIDE);

#pragma unroll
        for (int ks = 0; ks < 4; ks++) {
            const int kb = ks * 8;
            unsigned int af[2][4];
#pragma unroll
            for (int mt = 0; mt < 2; mt++) {
                int row = wm * 32 + mt * 16 + gid;
                af[mt][0] = Au[(size_t)row * PJ_STRIDE + kb + tid4];
                af[mt][1] = Au[(size_t)(row + 8) * PJ_STRIDE + kb + tid4];
                af[mt][2] = Au[(size_t)row * PJ_STRIDE + kb + tid4 + 4];
                af[mt][3] = Au[(size_t)(row + 8) * PJ_STRIDE + kb + tid4 + 4];
            }
            unsigned int bf[4][2];
#pragma unroll
            for (int nt = 0; nt < 4; nt++) {
                int col = wn * 32 + nt * 8 + gid;
                bf[nt][0] = Bu[(size_t)col * PJ_STRIDE + kb + tid4];
                bf[nt][1] = Bu[(size_t)col * PJ_STRIDE + kb + tid4 + 4];
            }
#pragma unroll
            for (int mt = 0; mt < 2; mt++)
#pragma unroll
                for (int nt = 0; nt < 4; nt++) {
                    asm volatile(
                        "mma.sync.aligned.m16n8k8.row.col.f32.tf32.tf32.f32 "
                        "{%0,%1,%2,%3}, {%4,%5,%6,%7}, {%8,%9}, {%0,%1,%2,%3};"
                        : "+f"(acc[mt][nt][0]), "+f"(acc[mt][nt][1]),
                          "+f"(acc[mt][nt][2]), "+f"(acc[mt][nt][3])
                        : "r"(af[mt][0]), "r"(af[mt][1]),
                          "r"(af[mt][2]), "r"(af[mt][3]),
                          "r"(bf[nt][0]), "r"(bf[nt][1]));
                }
        }

        // store prefetched tile into the other buffer
        if (t < 7) {
            unsigned int* a0 = (unsigned int*)&As[((size_t)nxt * 128 + lr) * PJ_STRIDE + lc * 4];
            unsigned int* a1 = (unsigned int*)&As[((size_t)nxt * 128 + lr + 64) * PJ_STRIDE + lc * 4];
            unsigned int* b0 = (unsigned int*)&Bs[((size_t)nxt * 128 + lr) * PJ_STRIDE + lc * 4];
            unsigned int* b1 = (unsigned int*)&Bs[((size_t)nxt * 128 + lr + 64) * PJ_STRIDE + lc * 4];
            a0[0]=f2tf32(sx0.x); a0[1]=f2tf32(sx0.y); a0[2]=f2tf32(sx0.z); a0[3]=f2tf32(sx0.w);
            a1[0]=f2tf32(sx1.x); a1[1]=f2tf32(sx1.y); a1[2]=f2tf32(sx1.z); a1[3]=f2tf32(sx1.w);
            b0[0]=f2tf32(sw0.x); b0[1]=f2tf32(sw0.y); b0[2]=f2tf32(sw0.z); b0[3]=f2tf32(sw0.w);
            b1[0]=f2tf32(sw1.x); b1[1]=f2tf32(sw1.y); b1[2]=f2tf32(sw1.z); b1[3]=f2tf32(sw1.w);
        }
        __syncthreads();
    }

    // epilogue: bias + store
#pragma unroll
    for (int mt = 0; mt < 2; mt++) {
        int r0 = i0 + wm * 32 + mt * 16 + gid;
#pragma unroll
        for (int nt = 0; nt < 4; nt++) {
            int c0 = wn * 32 + nt * 8 + 2 * tid4;
            float2 bias = *(const float2*)&Bv[c0];
            float* p0 = &out[(size_t)r0 * 384 + my * 128 + c0];
            float* p1 = &out[(size_t)(r0 + 8) * 384 + my * 128 + c0];
            *(float2*)p0 = make_float2(acc[mt][nt][0] + bias.x,
                                       acc[mt][nt][1] + bias.y);
            *(float2*)p1 = make_float2(acc[mt][nt][2] + bias.x,
                                       acc[mt][nt][3] + bias.y);
        }
    }
}

// ---------------------------------------------------------------------------
// Kernel A2: a[b][t] = sigmoid(dot(x[b][t], k1 - k2))
// ---------------------------------------------------------------------------
__global__ __launch_bounds__(256) void a_gate_kernel(
    const float* __restrict__ x, const float* __restrict__ k1k2,
    float* __restrict__ ga)
{
    const int warp = threadIdx.x >> 5, lane = threadIdx.x & 31;
    const int row = blockIdx.x * 8 + warp;
    const float* xr = x + (size_t)row * 256;
    float s = 0.f;
#pragma unroll
    for (int r = 0; r < 2; r++) {
        int k = lane * 4 + r * 128;
        float4 xv = *(const float4*)&xr[k];
        float4 a1 = *(const float4*)&k1k2[k];
        float4 a2 = *(const float4*)&k1k2[256 + k];
        s += xv.x * (a1.x - a2.x) + xv.y * (a1.y - a2.y) +
             xv.z * (a1.z - a2.z) + xv.w * (a1.w - a2.w);
    }
#pragma unroll
    for (int off = 16; off > 0; off >>= 1)
        s += __shfl_xor_sync(0xffffffffu, s, off);
    if (lane == 0) ga[row] = __fdividef(1.f, 1.f + __expf(-s));
}

// ---------------------------------------------------------------------------
// Kernel B: sequential recurrence. 128 CTAs x 2 batches, 512 threads.
//   u_r/u_h register-cached (64 regs); u_z streamed from transposed smem
//   (fixes register spill at the 128-reg/thread cap with 512 threads).
// ---------------------------------------------------------------------------
__global__ __launch_bounds__(512, 1) void rnn_kernel(
    const float* __restrict__ gX, const float* __restrict__ ga,
    const int* __restrict__ cor,
    const float* __restrict__ ur, const float* __restrict__ uz,
    const float* __restrict__ uh,
    float* __restrict__ out)
{
    extern __shared__ float sm[];
    float* m_sm   = sm;                    // [2][128]              256
    float* part   = sm + 256;              // [3][2][4*128]         3072
    float* xs     = sm + 256 + 3072;       // [2][384]              768
    float* a_sm   = xs + 768;              // [2][256]              512
    int*   cor_sm = (int*)(a_sm + 512);    // [2][256]              512
    unsigned long long* uzs =
        (unsigned long long*)(sm + 5120);  // [64 kpair][128 d]     16384 fl
    float* buf    = sm + 5120 + 16384;     // [2][257][64]          32896

    const int tid = threadIdx.x;
    const int b0  = blockIdx.x * 2;
    const int d   = tid & 127;
    const int q   = tid >> 7;
    const int kbase = q * 32;

    // register-cache u_r, u_h slices as packed (k, k+1) pairs (64 regs)
    unsigned long long urr[16], uhr[16];
#pragma unroll
    for (int kk = 0; kk < 16; kk++) {
        urr[kk] = *(const unsigned long long*)&ur[d * 128 + kbase + 2 * kk];
        uhr[kk] = *(const unsigned long long*)&uh[d * 128 + kbase + 2 * kk];
    }

    // u_z -> smem, transposed pair layout: uzs[kpair*128 + d] = (uz[d][2kp], uz[d][2kp+1])
    for (int idx = tid; idx < 64 * 128; idx += 512) {
        int kp = idx & 63;
        int dz = idx >> 6;
        uzs[kp * 128 + dz] = *(const unsigned long long*)&uz[dz * 128 + 2 * kp];
    }

    // init: m_0 = 0, buf[:,0,:] = 0; preload a and cor
    if (tid < 256) m_sm[tid] = 0.f;
    if (tid < 128) {
        int bb = tid >> 6;
        buf[bb * 16448 + (tid & 63)] = 0.f;
    }
    {
        int bb = tid >> 8, tt = tid & 255;
        a_sm[tid]   = ga[(size_t)(b0 + bb) * LL + tt];
        cor_sm[tid] = cor[(size_t)(b0 + bb) * LL + tt];
    }
    __syncthreads();

    const unsigned long long* m0p = (const unsigned long long*)&m_sm[kbase];
    const unsigned long long* m1p = (const unsigned long long*)&m_sm[128 + kbase];
    const unsigned long long* uzp = uzs + q * 16 * 128 + d;

    for (int t = 0; t < LL; t++) {
        // prefetch X[t] (hidden behind the matvec)
        const size_t base0 = ((size_t)b0 * LL + t) * 384;
        const size_t base1 = ((size_t)(b0 + 1) * LL + t) * 384;
        float xpre0 = (tid < 384) ? gX[base0 + tid] : gX[base1 + (tid - 384)];
        float xpre1 = (tid < 256) ? gX[base1 + 128 + tid] : 0.f;

        // matvec: 32-k slice, both batches; u_z from smem
        unsigned long long ar0 = 0ULL, ar1 = 0ULL;
        unsigned long long az0 = 0ULL, az1 = 0ULL;
        unsigned long long ah0 = 0ULL, ah1 = 0ULL;
#pragma unroll
        for (int kk = 0; kk < 16; kk++) {
            unsigned long long m0 = m0p[kk];
            unsigned long long m1 = m1p[kk];
            unsigned long long uzv = uzp[kk * 128];
            ar0 = ffma2(urr[kk], m0, ar0);
            ar1 = ffma2(urr[kk], m1, ar1);
            az0 = ffma2(uzv,     m0, az0);
            az1 = ffma2(uzv,     m1, az1);
            ah0 = ffma2(uhr[kk], m0, ah0);
            ah1 = ffma2(uhr[kk], m1, ah1);
        }
        {
            float2 f;
            f = unpack2(ar0); part[0 * 1024 + 0 * 512 + q * 128 + d] = f.x + f.y;
            f = unpack2(ar1); part[0 * 1024 + 1 * 512 + q * 128 + d] = f.x + f.y;
            f = unpack2(az0); part[1 * 1024 + 0 * 512 + q * 128 + d] = f.x + f.y;
            f = unpack2(az1); part[1 * 1024 + 1 * 512 + q * 128 + d] = f.x + f.y;
            f = unpack2(ah0); part[2 * 1024 + 0 * 512 + q * 128 + d] = f.x + f.y;
            f = unpack2(ah1); part[2 * 1024 + 1 * 512 + q * 128 + d] = f.x + f.y;
        }
        xs[tid] = xpre0;
        if (tid < 256) xs[512 + tid] = xpre1;
        __syncthreads();

        // nonlinearity + state update (256 threads: (bb, dd))
        if (tid < 256) {
            const int bb = tid >> 7;
            const int dd = tid & 127;
            const int pb = bb * 512 + dd;
            float sr = part[pb] + part[pb + 128] + part[pb + 256] + part[pb + 384];
            float sz = part[1024 + pb] + part[1024 + pb + 128] +
                       part[1024 + pb + 256] + part[1024 + pb + 384];
            float sh = part[2048 + pb] + part[2048 + pb + 128] +
                       part[2048 + pb + 256] + part[2048 + pb + 384];
            float xr = xs[bb * 384 + dd];
            float xz = xs[bb * 384 + 128 + dd];
            float xh = xs[bb * 384 + 256 + dd];

            float r  = __fdividef(1.f, 1.f + __expf(-(xr + sr)));
            float z  = __fdividef(1.f, 1.f + __expf(-(xz + sz)));
            // tanh(y) = 1 - 2/(e^{2y}+1)
            float ey = __expf(2.f * (xh + r * sh));
            float hv = 1.f - __fdividef(2.f, ey + 1.f);
            float mv = m_sm[bb * 128 + dd];
            float h  = (1.f - z) * mv + z * hv;

            out[(((size_t)(b0 + bb) * LL) + t) * DD + dd] = h;

            if (t + 1 < LL) {
                float an = a_sm[bb * 256 + t + 1];
                if (dd < HH) {
                    m_sm[bb * 128 + dd] = an * h;
                } else {
                    buf[bb * 16448 + (t + 1) * 64 + (dd - HH)] = h;
                    int cn = cor_sm[bb * 256 + t + 1];
                    int ie = (cn == 0) ? (t + 1) : cn;
                    m_sm[bb * 128 + dd] =
                        (1.f - an) * buf[bb * 16448 + ie * 64 + (dd - HH)];
                }
            }
        }
        __syncthreads();
    }
}

// ---------------------------------------------------------------------------
// launch
// ---------------------------------------------------------------------------
extern "C" void kernel_launch(void* const* d_in, const int* in_sizes, int n_in,
                              void* d_out, int out_size)
{
    (void)in_sizes; (void)n_in; (void)out_size;
    const float* x    = (const float*)d_in[0];
    const int*   cor  = (const int*)d_in[1];
    const float* w_r  = (const float*)d_in[2];
    const float* b_r  = (const float*)d_in[3];
    const float* u_r  = (const float*)d_in[4];
    const float* w_z  = (const float*)d_in[5];
    const float* b_z  = (const float*)d_in[6];
    const float* u_z  = (const float*)d_in[7];
    const float* w_h  = (const float*)d_in[8];
    const float* b_h  = (const float*)d_in[9];
    const float* u_h  = (const float*)d_in[10];
    const float* k1k2 = (const float*)d_in[11];
    float* out = (float*)d_out;

    float* gX; cudaGetSymbolAddress((void**)&gX, g_X);
    float* ga; cudaGetSymbolAddress((void**)&ga, g_a);

    // Kernel A: projections via tf32 tensor cores
    {
        const int smemA = 2 * 2 * 128 * PJ_STRIDE * 4;   // 73728 B
        cudaFuncSetAttribute(proj_gemm_tf32,
                             cudaFuncAttributeMaxDynamicSharedMemorySize, smemA);
        dim3 grid(BB * LL / 128, 3);
        proj_gemm_tf32<<<grid, 512, smemA>>>(x, w_r, b_r, w_z, b_z, w_h, b_h, gX);
    }
    // Kernel A2: attention gate
    a_gate_kernel<<<BB * LL / 8, 256>>>(x, k1k2, ga);

    // Kernel B: recurrence
    {
        const size_t smemB = (size_t)(5120 + 16384 + 32896) * sizeof(float); // 217600
        cudaFuncSetAttribute(rnn_kernel,
                             cudaFuncAttributeMaxDynamicSharedMemorySize,
                             (int)smemB);
        rnn_kernel<<<128, 512, smemB>>>(gX, ga, cor, u_r, u_z, u_h, out);
    }
}

// round 4
// speedup vs baseline: 1.4930x; 1.0631x over previous
#include <cuda_runtime.h>
#include <cuda_bf16.h>
#include <cstdint>

// Problem constants
#define BB   256   // batch
#define LL   256   // seq len
#define IN_  256   // input dim
#define DD   128   // hidden dim
#define HH   64    // DD/2

// ---------------------------------------------------------------------------
// packed f32x2 helpers (FFMA2)
// ---------------------------------------------------------------------------
__device__ __forceinline__ unsigned long long ffma2(unsigned long long a,
                                                    unsigned long long b,
                                                    unsigned long long c) {
    unsigned long long d;
    asm("fma.rn.f32x2 %0, %1, %2, %3;" : "=l"(d) : "l"(a), "l"(b), "l"(c));
    return d;
}
__device__ __forceinline__ unsigned long long packpair(float lo, float hi) {
    unsigned long long r;
    asm("mov.b64 %0, {%1, %2};" : "=l"(r) : "f"(lo), "f"(hi));
    return r;
}
__device__ __forceinline__ float2 unpack2(unsigned long long v) {
    float2 f;
    asm("mov.b64 {%0, %1}, %2;" : "=f"(f.x), "=f"(f.y) : "l"(v));
    return f;
}
__device__ __forceinline__ unsigned int f2tf32(float f) {
    unsigned int u;
    asm("cvt.rna.tf32.f32 %0, %1;" : "=r"(u) : "f"(f));
    return u;
}

// ---------------------------------------------------------------------------
// Scratch (device globals; no runtime allocation allowed)
// ---------------------------------------------------------------------------
__device__ float g_X[(size_t)BB * LL * 384];  // [b][t][mat*128+d]
__device__ float g_a[(size_t)BB * LL];        // attention gate a[b][t]

// ---------------------------------------------------------------------------
// Kernel A: projection GEMM via tf32 mma.sync (m16n8k8)  (unchanged from R3)
// ---------------------------------------------------------------------------
#define PJ_STRIDE 36
extern __shared__ float pj_sm[];

__global__ __launch_bounds__(512, 1) void proj_gemm_tf32(
    const float* __restrict__ x,
    const float* __restrict__ wr, const float* __restrict__ br,
    const float* __restrict__ wz, const float* __restrict__ bz,
    const float* __restrict__ wh, const float* __restrict__ bh,
    float* __restrict__ out)
{
    float* As = pj_sm;                                // [2][128][36]
    float* Bs = pj_sm + 2 * 128 * PJ_STRIDE;          // [2][128][36]

    const int my = blockIdx.y;
    const float* __restrict__ W  = (my == 0) ? wr : (my == 1 ? wz : wh);
    const float* __restrict__ Bv = (my == 0) ? br : (my == 1 ? bz : bh);

    const int tid  = threadIdx.x;
    const int lane = tid & 31;
    const int wid  = tid >> 5;
    const int wm   = wid & 3;
    const int wn   = wid >> 2;
    const int gid  = lane >> 2;
    const int tid4 = lane & 3;
    const int i0   = blockIdx.x * 128;

    const int lr = tid >> 3;
    const int lc = tid & 7;

    float acc[2][4][4];
#pragma unroll
    for (int a = 0; a < 2; a++)
#pragma unroll
        for (int b = 0; b < 4; b++)
#pragma unroll
            for (int c = 0; c < 4; c++) acc[a][b][c] = 0.f;

    float4 sx0, sx1, sw0, sw1;

    {
        const int k0 = 0;
        sx0 = *(const float4*)&x[(size_t)(i0 + lr)      * 256 + k0 + lc * 4];
        sx1 = *(const float4*)&x[(size_t)(i0 + lr + 64) * 256 + k0 + lc * 4];
        sw0 = *(const float4*)&W[(size_t)(lr)      * 256 + k0 + lc * 4];
        sw1 = *(const float4*)&W[(size_t)(lr + 64) * 256 + k0 + lc * 4];
        unsigned int* a0 = (unsigned int*)&As[(size_t)lr * PJ_STRIDE + lc * 4];
        unsigned int* a1 = (unsigned int*)&As[(size_t)(lr + 64) * PJ_STRIDE + lc * 4];
        unsigned int* b0 = (unsigned int*)&Bs[(size_t)lr * PJ_STRIDE + lc * 4];
        unsigned int* b1 = (unsigned int*)&Bs[(size_t)(lr + 64) * PJ_STRIDE + lc * 4];
        a0[0]=f2tf32(sx0.x); a0[1]=f2tf32(sx0.y); a0[2]=f2tf32(sx0.z); a0[3]=f2tf32(sx0.w);
        a1[0]=f2tf32(sx1.x); a1[1]=f2tf32(sx1.y); a1[2]=f2tf32(sx1.z); a1[3]=f2tf32(sx1.w);
        b0[0]=f2tf32(sw0.x); b0[1]=f2tf32(sw0.y); b0[2]=f2tf32(sw0.z); b0[3]=f2tf32(sw0.w);
        b1[0]=f2tf32(sw1.x); b1[1]=f2tf32(sw1.y); b1[2]=f2tf32(sw1.z); b1[3]=f2tf32(sw1.w);
    }
    __syncthreads();

#pragma unroll 1
    for (int t = 0; t < 8; t++) {
        const int cur = t & 1;
        const int nxt = cur ^ 1;
        if (t < 7) {
            const int k0 = (t + 1) * 32;
            sx0 = *(const float4*)&x[(size_t)(i0 + lr)      * 256 + k0 + lc * 4];
            sx1 = *(const float4*)&x[(size_t)(i0 + lr + 64) * 256 + k0 + lc * 4];
            sw0 = *(const float4*)&W[(size_t)(lr)      * 256 + k0 + lc * 4];
            sw1 = *(const float4*)&W[(size_t)(lr + 64) * 256 + k0 + lc * 4];
        }

        const unsigned int* Au = (const unsigned int*)(As + (size_t)cur * 128 * PJ_STRIDE);
        const unsigned int* Bu = (const unsigned int*)(Bs + (size_t)cur * 128 * PJ_STRIDE);

#pragma unroll
        for (int ks = 0; ks < 4; ks++) {
            const int kb = ks * 8;
            unsigned int af[2][4];
#pragma unroll
            for (int mt = 0; mt < 2; mt++) {
                int row = wm * 32 + mt * 16 + gid;
                af[mt][0] = Au[(size_t)row * PJ_STRIDE + kb + tid4];
                af[mt][1] = Au[(size_t)(row + 8) * PJ_STRIDE + kb + tid4];
                af[mt][2] = Au[(size_t)row * PJ_STRIDE + kb + tid4 + 4];
                af[mt][3] = Au[(size_t)(row + 8) * PJ_STRIDE + kb + tid4 + 4];
            }
            unsigned int bf[4][2];
#pragma unroll
            for (int nt = 0; nt < 4; nt++) {
                int col = wn * 32 + nt * 8 + gid;
                bf[nt][0] = Bu[(size_t)col * PJ_STRIDE + kb + tid4];
                bf[nt][1] = Bu[(size_t)col * PJ_STRIDE + kb + tid4 + 4];
            }
#pragma unroll
            for (int mt = 0; mt < 2; mt++)
#pragma unroll
                for (int nt = 0; nt < 4; nt++) {
                    asm volatile(
                        "mma.sync.aligned.m16n8k8.row.col.f32.tf32.tf32.f32 "
                        "{%0,%1,%2,%3}, {%4,%5,%6,%7}, {%8,%9}, {%0,%1,%2,%3};"
                        : "+f"(acc[mt][nt][0]), "+f"(acc[mt][nt][1]),
                          "+f"(acc[mt][nt][2]), "+f"(acc[mt][nt][3])
                        : "r"(af[mt][0]), "r"(af[mt][1]),
                          "r"(af[mt][2]), "r"(af[mt][3]),
                          "r"(bf[nt][0]), "r"(bf[nt][1]));
                }
        }

        if (t < 7) {
            unsigned int* a0 = (unsigned int*)&As[((size_t)nxt * 128 + lr) * PJ_STRIDE + lc * 4];
            unsigned int* a1 = (unsigned int*)&As[((size_t)nxt * 128 + lr + 64) * PJ_STRIDE + lc * 4];
            unsigned int* b0 = (unsigned int*)&Bs[((size_t)nxt * 128 + lr) * PJ_STRIDE + lc * 4];
            unsigned int* b1 = (unsigned int*)&Bs[((size_t)nxt * 128 + lr + 64) * PJ_STRIDE + lc * 4];
            a0[0]=f2tf32(sx0.x); a0[1]=f2tf32(sx0.y); a0[2]=f2tf32(sx0.z); a0[3]=f2tf32(sx0.w);
            a1[0]=f2tf32(sx1.x); a1[1]=f2tf32(sx1.y); a1[2]=f2tf32(sx1.z); a1[3]=f2tf32(sx1.w);
            b0[0]=f2tf32(sw0.x); b0[1]=f2tf32(sw0.y); b0[2]=f2tf32(sw0.z); b0[3]=f2tf32(sw0.w);
            b1[0]=f2tf32(sw1.x); b1[1]=f2tf32(sw1.y); b1[2]=f2tf32(sw1.z); b1[3]=f2tf32(sw1.w);
        }
        __syncthreads();
    }

#pragma unroll
    for (int mt = 0; mt < 2; mt++) {
        int r0 = i0 + wm * 32 + mt * 16 + gid;
#pragma unroll
        for (int nt = 0; nt < 4; nt++) {
            int c0 = wn * 32 + nt * 8 + 2 * tid4;
            float2 bias = *(const float2*)&Bv[c0];
            float* p0 = &out[(size_t)r0 * 384 + my * 128 + c0];
            float* p1 = &out[(size_t)(r0 + 8) * 384 + my * 128 + c0];
            *(float2*)p0 = make_float2(acc[mt][nt][0] + bias.x,
                                       acc[mt][nt][1] + bias.y);
            *(float2*)p1 = make_float2(acc[mt][nt][2] + bias.x,
                                       acc[mt][nt][3] + bias.y);
        }
    }
}

// ---------------------------------------------------------------------------
// Kernel A2: a[b][t] = sigmoid(dot(x[b][t], k1 - k2))
// ---------------------------------------------------------------------------
__global__ __launch_bounds__(256) void a_gate_kernel(
    const float* __restrict__ x, const float* __restrict__ k1k2,
    float* __restrict__ ga)
{
    const int warp = threadIdx.x >> 5, lane = threadIdx.x & 31;
    const int row = blockIdx.x * 8 + warp;
    const float* xr = x + (size_t)row * 256;
    float s = 0.f;
#pragma unroll
    for (int r = 0; r < 2; r++) {
        int k = lane * 4 + r * 128;
        float4 xv = *(const float4*)&xr[k];
        float4 a1 = *(const float4*)&k1k2[k];
        float4 a2 = *(const float4*)&k1k2[256 + k];
        s += xv.x * (a1.x - a2.x) + xv.y * (a1.y - a2.y) +
             xv.z * (a1.z - a2.z) + xv.w * (a1.w - a2.w);
    }
#pragma unroll
    for (int off = 16; off > 0; off >>= 1)
        s += __shfl_xor_sync(0xffffffffu, s, off);
    if (lane == 0) ga[row] = __fdividef(1.f, 1.f + __expf(-s));
}

// ---------------------------------------------------------------------------
// Kernel B v3: sequential recurrence. 128 CTAs x 2 batches, 256 threads.
//   tid = 2*d + q.  q = k-half AND batch assignment for the update phase.
//   All of U (3 gates x 32 ull = 192 regs) in registers -> zero U smem traffic.
//   Butterfly shuffle (xor 1) completes the k reduction -> no partials smem.
//   m double-buffered by step parity -> ONE __syncthreads() per step.
// ---------------------------------------------------------------------------
__global__ __launch_bounds__(256, 1) void rnn_kernel(
    const float* __restrict__ gX, const float* __restrict__ ga,
    const int* __restrict__ cor,
    const float* __restrict__ ur, const float* __restrict__ uz,
    const float* __restrict__ uh,
    float* __restrict__ out)
{
    extern __shared__ float sm[];
    float* m_sm   = sm;                    // [2 parity][2 b][128]   512
    float* a_sm   = sm + 512;              // [2][256]               512
    int*   cor_sm = (int*)(sm + 1024);     // [2][256]               512
    float* buf    = sm + 1536;             // [2][257][64]           32896

    const int tid = threadIdx.x;
    const int q   = tid & 1;      // k-half; also batch handled in update
    const int d   = tid >> 1;     // 0..127
    const int b0  = blockIdx.x * 2;
    const int kb  = q * 64;

    // ---- U register cache: rows d of u_r/u_z/u_h, k in [kb, kb+64) ----
    unsigned long long urr[32], uzr[32], uhr[32];
#pragma unroll
    for (int j = 0; j < 32; j++) {
        urr[j] = *(const unsigned long long*)&ur[d * 128 + kb + 2 * j];
        uzr[j] = *(const unsigned long long*)&uz[d * 128 + kb + 2 * j];
        uhr[j] = *(const unsigned long long*)&uh[d * 128 + kb + 2 * j];
    }

    // ---- init ----
    m_sm[tid] = 0.f;                              // parity 0: [2][128]
    if (tid < 128) buf[(tid >> 6) * 16448 + (tid & 63)] = 0.f;
#pragma unroll
    for (int i = tid; i < 512; i += 256) {
        int bb = i >> 8, tt = i & 255;
        a_sm[i]   = ga[(size_t)(b0 + bb) * LL + tt];
        cor_sm[i] = cor[(size_t)(b0 + bb) * LL + tt];
    }
    __syncthreads();

    // prefetch X for t=0, batch q
    size_t xbase = ((size_t)(b0 + q) * LL) * 384 + d;
    float xr = gX[xbase], xz = gX[xbase + 128], xh = gX[xbase + 256];

    for (int t = 0; t < LL; t++) {
        const int par = t & 1;
        const int np  = par ^ 1;

        // ---- matvec over k-half [kb,kb+64), both batches ----
        const float4* m0 = (const float4*)&m_sm[par * 256 + kb];
        const float4* m1 = (const float4*)&m_sm[par * 256 + 128 + kb];
        unsigned long long ar0 = 0ULL, az0 = 0ULL, ah0 = 0ULL;
        unsigned long long ar1 = 0ULL, az1 = 0ULL, ah1 = 0ULL;
#pragma unroll
        for (int j = 0; j < 16; j++) {
            float4 v0 = m0[j];
            float4 v1 = m1[j];
            unsigned long long p0a = packpair(v0.x, v0.y);
            unsigned long long p0b = packpair(v0.z, v0.w);
            unsigned long long p1a = packpair(v1.x, v1.y);
            unsigned long long p1b = packpair(v1.z, v1.w);
            ar0 = ffma2(urr[2*j],   p0a, ar0);
            az0 = ffma2(uzr[2*j],   p0a, az0);
            ah0 = ffma2(uhr[2*j],   p0a, ah0);
            ar1 = ffma2(urr[2*j],   p1a, ar1);
            az1 = ffma2(uzr[2*j],   p1a, az1);
            ah1 = ffma2(uhr[2*j],   p1a, ah1);
            ar0 = ffma2(urr[2*j+1], p0b, ar0);
            az0 = ffma2(uzr[2*j+1], p0b, az0);
            ah0 = ffma2(uhr[2*j+1], p0b, ah0);
            ar1 = ffma2(urr[2*j+1], p1b, ar1);
            az1 = ffma2(uzr[2*j+1], p1b, az1);
            ah1 = ffma2(uhr[2*j+1], p1b, ah1);
        }

        // horizontal add + butterfly (xor 1) -> full-k sums in both lanes
        float2 f;
        f = unpack2(ar0); float sr0 = f.x + f.y;
        f = unpack2(az0); float sz0 = f.x + f.y;
        f = unpack2(ah0); float sh0 = f.x + f.y;
        f = unpack2(ar1); float sr1 = f.x + f.y;
        f = unpack2(az1); float sz1 = f.x + f.y;
        f = unpack2(ah1); float sh1 = f.x + f.y;
        sr0 += __shfl_xor_sync(0xffffffffu, sr0, 1);
        sz0 += __shfl_xor_sync(0xffffffffu, sz0, 1);
        sh0 += __shfl_xor_sync(0xffffffffu, sh0, 1);
        sr1 += __shfl_xor_sync(0xffffffffu, sr1, 1);
        sz1 += __shfl_xor_sync(0xffffffffu, sz1, 1);
        sh1 += __shfl_xor_sync(0xffffffffu, sh1, 1);

        // this lane handles batch (b0+q)
        float sr = q ? sr1 : sr0;
        float sz = q ? sz1 : sz0;
        float sh = q ? sh1 : sh0;

        // ---- nonlinearity + state update (all 256 threads) ----
        float r  = __fdividef(1.f, 1.f + __expf(-(xr + sr)));
        float z  = __fdividef(1.f, 1.f + __expf(-(xz + sz)));
        float ey = __expf(2.f * (xh + r * sh));
        float hv = 1.f - __fdividef(2.f, ey + 1.f);
        float mv = m_sm[par * 256 + q * 128 + d];
        float h  = (1.f - z) * mv + z * hv;

        out[(((size_t)(b0 + q) * LL) + t) * DD + d] = h;

        if (t + 1 < LL) {
            // prefetch X for t+1 (consumed ~1 step later)
            xbase = ((size_t)(b0 + q) * LL + (t + 1)) * 384 + d;
            xr = gX[xbase]; xz = gX[xbase + 128]; xh = gX[xbase + 256];

            float an = a_sm[q * 256 + t + 1];
            if (d < HH) {
                m_sm[np * 256 + q * 128 + d] = an * h;
            } else {
                buf[q * 16448 + (t + 1) * 64 + (d - HH)] = h;
                int cn = cor_sm[q * 256 + t + 1];
                int ie = (cn == 0) ? (t + 1) : cn;
                m_sm[np * 256 + q * 128 + d] =
                    (1.f - an) * buf[q * 16448 + ie * 64 + (d - HH)];
            }
        }
        __syncthreads();
    }
}

// ---------------------------------------------------------------------------
// launch
// ---------------------------------------------------------------------------
extern "C" void kernel_launch(void* const* d_in, const int* in_sizes, int n_in,
                              void* d_out, int out_size)
{
    (void)in_sizes; (void)n_in; (void)out_size;
    const float* x    = (const float*)d_in[0];
    const int*   cor  = (const int*)d_in[1];
    const float* w_r  = (const float*)d_in[2];
    const float* b_r  = (const float*)d_in[3];
    const float* u_r  = (const float*)d_in[4];
    const float* w_z  = (const float*)d_in[5];
    const float* b_z  = (const float*)d_in[6];
    const float* u_z  = (const float*)d_in[7];
    const float* w_h  = (const float*)d_in[8];
    const float* b_h  = (const float*)d_in[9];
    const float* u_h  = (const float*)d_in[10];
    const float* k1k2 = (const float*)d_in[11];
    float* out = (float*)d_out;

    float* gX; cudaGetSymbolAddress((void**)&gX, g_X);
    float* ga; cudaGetSymbolAddress((void**)&ga, g_a);

    // Kernel A: projections via tf32 tensor cores
    {
        const int smemA = 2 * 2 * 128 * PJ_STRIDE * 4;   // 73728 B
        cudaFuncSetAttribute(proj_gemm_tf32,
                             cudaFuncAttributeMaxDynamicSharedMemorySize, smemA);
        dim3 grid(BB * LL / 128, 3);
        proj_gemm_tf32<<<grid, 512, smemA>>>(x, w_r, b_r, w_z, b_z, w_h, b_h, gX);
    }
    // Kernel A2: attention gate
    a_gate_kernel<<<BB * LL / 8, 256>>>(x, k1k2, ga);

    // Kernel B: recurrence
    {
        const size_t smemB = (size_t)(512 + 512 + 512 + 2 * 257 * 64)
                             * sizeof(float);            // 137728 B
        cudaFuncSetAttribute(rnn_kernel,
                             cudaFuncAttributeMaxDynamicSharedMemorySize,
                             (int)smemB);
        rnn_kernel<<<128, 256, smemB>>>(gX, ga, cor, u_r, u_z, u_h, out);
    }
}